// round 2
// baseline (speedup 1.0000x reference)
#include <cuda_runtime.h>

#define BATCH 2
#define SEQ   2048
#define DM    1024
#define NH    16
#define HD    64
#define MROWS (BATCH*SEQ)

// Scratch (allocation-free rule: __device__ globals)
__device__ float g_Q[BATCH*NH*SEQ*HD];
__device__ float g_K[BATCH*NH*SEQ*HD];
__device__ float g_V[BATCH*NH*SEQ*HD];
__device__ float g_A[BATCH*SEQ*DM];

// ---------------------------------------------------------------------------
// C[M,N] = X[M,K] * W[N,K]^T   (NT gemm, both row-major, contiguous in K)
// 64x64 block tile, BK=16, 256 threads, 4x4 microtile per thread.
// Smem stored transposed: Xs[k][m], Ws[k][n] -> conflict-free LDS.128 on b,
// broadcast on a.
// HEAD_LAYOUT: scatter output to [b, h, s, d] (h = col/64, d = col%64).
// ---------------------------------------------------------------------------
template<bool HEAD_LAYOUT>
__global__ void __launch_bounds__(256) gemm_nt(
    const float* __restrict__ X, const float* __restrict__ W,
    float* __restrict__ C, int M, int N, int K)
{
    __shared__ float Xs[16][64];
    __shared__ float Ws[16][64];

    const int tid = threadIdx.x;
    const int tx = tid & 15, ty = tid >> 4;
    const int m0 = blockIdx.y << 6, n0 = blockIdx.x << 6;
    const int lr = tid >> 2;            // 0..63: tile row to load
    const int lc = (tid & 3) << 2;      // 0,4,8,12: k-offset to load

    const float* Xp = X + (size_t)(m0 + lr) * K + lc;
    const float* Wp = W + (size_t)(n0 + lr) * K + lc;

    float acc[4][4];
    #pragma unroll
    for (int i = 0; i < 4; i++)
        #pragma unroll
        for (int j = 0; j < 4; j++) acc[i][j] = 0.f;

    for (int k0 = 0; k0 < K; k0 += 16) {
        float4 xv = *(const float4*)(Xp + k0);
        float4 wv = *(const float4*)(Wp + k0);
        __syncthreads();
        Xs[lc+0][lr] = xv.x; Xs[lc+1][lr] = xv.y;
        Xs[lc+2][lr] = xv.z; Xs[lc+3][lr] = xv.w;
        Ws[lc+0][lr] = wv.x; Ws[lc+1][lr] = wv.y;
        Ws[lc+2][lr] = wv.z; Ws[lc+3][lr] = wv.w;
        __syncthreads();
        #pragma unroll
        for (int k = 0; k < 16; k++) {
            float4 a = *(const float4*)&Xs[k][ty << 2];
            float4 b = *(const float4*)&Ws[k][tx << 2];
            acc[0][0] += a.x*b.x; acc[0][1] += a.x*b.y; acc[0][2] += a.x*b.z; acc[0][3] += a.x*b.w;
            acc[1][0] += a.y*b.x; acc[1][1] += a.y*b.y; acc[1][2] += a.y*b.z; acc[1][3] += a.y*b.w;
            acc[2][0] += a.z*b.x; acc[2][1] += a.z*b.y; acc[2][2] += a.z*b.z; acc[2][3] += a.z*b.w;
            acc[3][0] += a.w*b.x; acc[3][1] += a.w*b.y; acc[3][2] += a.w*b.z; acc[3][3] += a.w*b.w;
        }
    }

    #pragma unroll
    for (int i = 0; i < 4; i++) {
        int row = m0 + (ty << 2) + i;
        int col = n0 + (tx << 2);
        float4 v = make_float4(acc[i][0], acc[i][1], acc[i][2], acc[i][3]);
        size_t idx;
        if (HEAD_LAYOUT) {
            int b = row >> 11, s = row & (SEQ - 1);
            int h = col >> 6,  d = col & (HD - 1);
            idx = ((size_t)((b * NH + h) * SEQ + s)) * HD + d;
        } else {
            idx = (size_t)row * N + col;
        }
        *(float4*)(C + idx) = v;
    }
}

// ---------------------------------------------------------------------------
// Causal flash attention, fp32. One CTA per (bh, 64-row q-tile).
// QsT/KsT stored transposed [k][row] for conflict-free LDS.128; KsT reused as
// P[row][col] after S is register-resident. Online-softmax stats (m, l) live
// in registers, replicated across the 16 lanes sharing a row; reductions via
// __shfl_xor_sync over offsets 8..1 (stays inside the 16-lane row group).
// Output written directly in [b, s, h*d] layout for the O-projection gemm.
// ---------------------------------------------------------------------------
__global__ void __launch_bounds__(256) flash_attn(
    const float* __restrict__ Q, const float* __restrict__ K,
    const float* __restrict__ V, float* __restrict__ A)
{
    __shared__ float QsT[64][64];   // [k][q-row]
    __shared__ float KsT[64][64];   // [k][k-col]; reused as P[row][col]
    __shared__ float Vs[64][64];    // [k-row][d]

    const int qt = blockIdx.x;                 // q tile 0..31
    const int bh = blockIdx.y;                 // 0..31
    const int b  = bh >> 4, h = bh & 15;
    const float* Qb = Q + (size_t)bh * SEQ * HD;
    const float* Kb = K + (size_t)bh * SEQ * HD;
    const float* Vb = V + (size_t)bh * SEQ * HD;

    const int tid = threadIdx.x;
    const int tx = tid & 15, ty = tid >> 4;
    const int lr = tid >> 2;              // 0..63: tile row to load
    const int lc = (tid & 3) << 4;        // 0,16,32,48: col offset (16 floats)

    // Load Q tile transposed
    {
        const float* qp = Qb + (size_t)(qt * 64 + lr) * HD + lc;
        #pragma unroll
        for (int u = 0; u < 4; u++) {
            float4 v = *(const float4*)(qp + u * 4);
            QsT[lc + u*4 + 0][lr] = v.x;
            QsT[lc + u*4 + 1][lr] = v.y;
            QsT[lc + u*4 + 2][lr] = v.z;
            QsT[lc + u*4 + 3][lr] = v.w;
        }
    }

    float m_[4], l_[4], o[4][4];
    #pragma unroll
    for (int i = 0; i < 4; i++) {
        m_[i] = -1e30f; l_[i] = 0.f;
        #pragma unroll
        for (int j = 0; j < 4; j++) o[i][j] = 0.f;
    }

    for (int kt = 0; kt <= qt; kt++) {
        __syncthreads();   // previous iter's P/V reads done before overwrite
        {
            const float* kp = Kb + (size_t)(kt * 64 + lr) * HD + lc;
            const float* vp = Vb + (size_t)(kt * 64 + lr) * HD + lc;
            #pragma unroll
            for (int u = 0; u < 4; u++) {
                float4 kv = *(const float4*)(kp + u * 4);
                KsT[lc + u*4 + 0][lr] = kv.x;
                KsT[lc + u*4 + 1][lr] = kv.y;
                KsT[lc + u*4 + 2][lr] = kv.z;
                KsT[lc + u*4 + 3][lr] = kv.w;
                float4 vv = *(const float4*)(vp + u * 4);
                *(float4*)&Vs[lr][lc + u * 4] = vv;
            }
        }
        __syncthreads();   // tiles visible (also covers QsT on first iter)

        // S = Q K^T (register 4x4 per thread)
        float s[4][4];
        #pragma unroll
        for (int i = 0; i < 4; i++)
            #pragma unroll
            for (int j = 0; j < 4; j++) s[i][j] = 0.f;

        #pragma unroll 8
        for (int k = 0; k < 64; k++) {
            float4 a  = *(const float4*)&QsT[k][ty << 2];
            float4 bk = *(const float4*)&KsT[k][tx << 2];
            s[0][0] += a.x*bk.x; s[0][1] += a.x*bk.y; s[0][2] += a.x*bk.z; s[0][3] += a.x*bk.w;
            s[1][0] += a.y*bk.x; s[1][1] += a.y*bk.y; s[1][2] += a.y*bk.z; s[1][3] += a.y*bk.w;
            s[2][0] += a.z*bk.x; s[2][1] += a.z*bk.y; s[2][2] += a.z*bk.z; s[2][3] += a.z*bk.w;
            s[3][0] += a.w*bk.x; s[3][1] += a.w*bk.y; s[3][2] += a.w*bk.z; s[3][3] += a.w*bk.w;
        }

        // scale + causal mask + online softmax (row stats in regs, shfl reduce)
        float p[4][4];
        const bool diag = (kt == qt);
        #pragma unroll
        for (int i = 0; i < 4; i++) {
            float rmax = -1e30f;
            #pragma unroll
            for (int j = 0; j < 4; j++) {
                float sc = s[i][j] * 0.125f;         // 1/sqrt(64)
                if (diag && ((tx << 2) + j) > ((ty << 2) + i)) sc = -1e8f;
                s[i][j] = sc;
                rmax = fmaxf(rmax, sc);
            }
            #pragma unroll
            for (int off = 8; off > 0; off >>= 1)
                rmax = fmaxf(rmax, __shfl_xor_sync(0xffffffffu, rmax, off));
            float nm = fmaxf(m_[i], rmax);
            float alpha = __expf(m_[i] - nm);
            float rsum = 0.f;
            #pragma unroll
            for (int j = 0; j < 4; j++) {
                float pv = __expf(s[i][j] - nm);
                p[i][j] = pv;
                rsum += pv;
            }
            #pragma unroll
            for (int off = 8; off > 0; off >>= 1)
                rsum += __shfl_xor_sync(0xffffffffu, rsum, off);
            l_[i] = l_[i] * alpha + rsum;
            m_[i] = nm;
            #pragma unroll
            for (int j = 0; j < 4; j++) o[i][j] *= alpha;
        }

        __syncthreads();   // done reading KsT as K
        // write P into KsT buffer as P[row][col]
        float* Ps = &KsT[0][0];
        #pragma unroll
        for (int i = 0; i < 4; i++)
            *(float4*)&Ps[(((ty << 2) + i) << 6) + (tx << 2)] =
                make_float4(p[i][0], p[i][1], p[i][2], p[i][3]);
        __syncthreads();

        // O += P V
        #pragma unroll 8
        for (int kk = 0; kk < 64; kk++) {
            float4 v = *(const float4*)&Vs[kk][tx << 2];
            #pragma unroll
            for (int i = 0; i < 4; i++) {
                float pv = Ps[(((ty << 2) + i) << 6) + kk];  // broadcast
                o[i][0] += pv * v.x;
                o[i][1] += pv * v.y;
                o[i][2] += pv * v.z;
                o[i][3] += pv * v.w;
            }
        }
    }

    // normalize + write in [b, s, h*d] layout
    #pragma unroll
    for (int i = 0; i < 4; i++) {
        float inv = 1.0f / l_[i];
        int qrow = qt * 64 + (ty << 2) + i;
        float* op = A + ((size_t)(b * SEQ + qrow)) * DM + h * HD + (tx << 2);
        *(float4*)op = make_float4(o[i][0]*inv, o[i][1]*inv, o[i][2]*inv, o[i][3]*inv);
    }
}

// ---------------------------------------------------------------------------

extern "C" void kernel_launch(void* const* d_in, const int* in_sizes, int n_in,
                              void* d_out, int out_size)
{
    (void)in_sizes; (void)n_in; (void)out_size;
    const float* x  = (const float*)d_in[0];
    const float* wq = (const float*)d_in[1];
    const float* wk = (const float*)d_in[2];
    const float* wv = (const float*)d_in[3];
    const float* wo = (const float*)d_in[4];

    float *q, *k, *v, *a;
    cudaGetSymbolAddress((void**)&q, g_Q);
    cudaGetSymbolAddress((void**)&k, g_K);
    cudaGetSymbolAddress((void**)&v, g_V);
    cudaGetSymbolAddress((void**)&a, g_A);

    dim3 blk(256);
    dim3 grid_g(DM / 64, MROWS / 64);      // (16, 64)
    gemm_nt<true ><<<grid_g, blk>>>(x, wq, q, MROWS, DM, DM);
    gemm_nt<true ><<<grid_g, blk>>>(x, wk, k, MROWS, DM, DM);
    gemm_nt<true ><<<grid_g, blk>>>(x, wv, v, MROWS, DM, DM);

    dim3 grid_a(SEQ / 64, BATCH * NH);     // (32, 32)
    flash_attn<<<grid_a, blk>>>(q, k, v, a);

    gemm_nt<false><<<grid_g, blk>>>(a, wo, (float*)d_out, MROWS, DM, DM);
}

// round 11
// speedup vs baseline: 1.6999x; 1.6999x over previous
#include <cuda_runtime.h>
#include <cuda_bf16.h>
#include <cstdint>

#define BATCH 2
#define SEQ   2048
#define DM    1024
#define NH    16
#define HD    64
#define MROWS (BATCH*SEQ)
#define K3    (3*DM)          // triple-interleaved K: A=(hi,lo,hi), B=(hi,hi,lo)

// ---------------------------------------------------------------------------
// Scratch (allocation-free rule: __device__ globals)
// ---------------------------------------------------------------------------
__device__ float g_Q[BATCH*NH*SEQ*HD];
__device__ float g_K[BATCH*NH*SEQ*HD];
__device__ float g_V[BATCH*NH*SEQ*HD];
__device__ float g_A[MROWS*DM];
__device__ __nv_bfloat16 g_X3[(size_t)MROWS*K3];     // in_features  (A-type triple)
__device__ __nv_bfloat16 g_W3[(size_t)4*DM*K3];      // 4 weights    (B-type triple)
__device__ __nv_bfloat16 g_A3[(size_t)MROWS*K3];     // attn out     (A-type triple)

// ---------------------------------------------------------------------------
// fp32 -> triple-interleaved bf16 along K.
//   A_TYPE: (hi, lo, hi)   B-type: (hi, hi, lo)
//   dot(tripA, tripB) = hi*hi + lo*hi + hi*lo   (drops lo*lo ~ 2^-18)
// Each thread processes 2 floats -> 6 bf16 -> 3 x b32 stores.
// ---------------------------------------------------------------------------
template<bool A_TYPE>
__global__ void split3(const float* __restrict__ src,
                       __nv_bfloat16* __restrict__ dst, int n2)
{
    int i = blockIdx.x * blockDim.x + threadIdx.x;
    int stride = gridDim.x * blockDim.x;
    __nv_bfloat162* d2 = (__nv_bfloat162*)dst;
    for (; i < n2; i += stride) {
        float2 x = ((const float2*)src)[i];
        __nv_bfloat16 hx = __float2bfloat16(x.x);
        __nv_bfloat16 hy = __float2bfloat16(x.y);
        __nv_bfloat16 lx = __float2bfloat16(x.x - __bfloat162float(hx));
        __nv_bfloat16 ly = __float2bfloat16(x.y - __bfloat162float(hy));
        if (A_TYPE) {
            // [hx, lx, hx,  hy, ly, hy]
            d2[i*3+0] = __halves2bfloat162(hx, lx);
            d2[i*3+1] = __halves2bfloat162(hx, hy);
            d2[i*3+2] = __halves2bfloat162(ly, hy);
        } else {
            // [hx, hx, lx,  hy, hy, ly]
            d2[i*3+0] = __halves2bfloat162(hx, hx);
            d2[i*3+1] = __halves2bfloat162(lx, hy);
            d2[i*3+2] = __halves2bfloat162(hy, ly);
        }
    }
}

// ---------------------------------------------------------------------------
// HMMA helpers
// ---------------------------------------------------------------------------
#define CP_ASYNC16(dst, src) \
    asm volatile("cp.async.cg.shared.global [%0], [%1], 16;" :: "r"(dst), "l"(src))
#define CP_COMMIT() asm volatile("cp.async.commit_group;" ::: "memory")
#define CP_WAIT1()  asm volatile("cp.async.wait_group 1;" ::: "memory")

__device__ __forceinline__ uint32_t smem_u32(const void* p) {
    uint32_t a;
    asm("{ .reg .u64 t; cvta.to.shared.u64 t, %1; cvt.u32.u64 %0, t; }" : "=r"(a) : "l"(p));
    return a;
}

__device__ __forceinline__ void ldmx4(uint32_t* r, uint32_t addr) {
    asm volatile("ldmatrix.sync.aligned.m8n8.x4.shared.b16 {%0,%1,%2,%3}, [%4];"
                 : "=r"(r[0]), "=r"(r[1]), "=r"(r[2]), "=r"(r[3]) : "r"(addr));
}

__device__ __forceinline__ void mma_bf16(float* c, const uint32_t* a, const uint32_t* b) {
    asm volatile(
        "mma.sync.aligned.m16n8k16.row.col.f32.bf16.bf16.f32 "
        "{%0,%1,%2,%3}, {%4,%5,%6,%7}, {%8,%9}, {%0,%1,%2,%3};"
        : "+f"(c[0]), "+f"(c[1]), "+f"(c[2]), "+f"(c[3])
        : "r"(a[0]), "r"(a[1]), "r"(a[2]), "r"(a[3]), "r"(b[0]), "r"(b[1]));
}

// ---------------------------------------------------------------------------
// bf16 HMMA GEMM:  C[M,N] = A3[M,K3] * B3[N,K3]^T   (K3 = triple-interleaved)
// CTA tile 128x128, BK=64 (128B swizzled rows), 3-stage cp.async pipeline,
// 8 warps in 4(M) x 2(N), warp tile 32x64, mma.m16n8k16 bf16 -> fp32.
// ---------------------------------------------------------------------------
#define GEMM_STAGES 3
#define GEMM_SMEM   (GEMM_STAGES * 32768)

template<bool HEAD_LAYOUT>
__global__ void __launch_bounds__(256)
gemm_hmma(const __nv_bfloat16* __restrict__ A3,
          const __nv_bfloat16* __restrict__ B3,
          float* __restrict__ C)
{
    extern __shared__ char dsm[];
    const uint32_t sb = smem_u32(dsm);
    const int t = threadIdx.x;
    const int lane = t & 31, wid = t >> 5;
    const int wm = wid & 3, wn = wid >> 2;          // warp grid 4x2
    const int m0 = blockIdx.y << 7, n0 = blockIdx.x << 7;

    float acc[2][8][4];
    #pragma unroll
    for (int mi = 0; mi < 2; mi++)
        #pragma unroll
        for (int ni = 0; ni < 8; ni++)
            #pragma unroll
            for (int j = 0; j < 4; j++) acc[mi][ni][j] = 0.f;

    auto load_stage = [&](int slot, int kt) {
        const uint32_t sa  = sb + (uint32_t)slot * 32768u;
        const uint32_t sbm = sa + 16384u;
        const int k0 = kt << 6;
        #pragma unroll
        for (int i = 0; i < 4; i++) {
            const int lin = t + (i << 8);
            const int row = lin >> 3, c8 = lin & 7;
            const uint32_t soff = (uint32_t)(row * 128 + ((c8 ^ (row & 7)) << 4));
            CP_ASYNC16(sa  + soff, A3 + (size_t)(m0 + row) * K3 + k0 + c8 * 8);
            CP_ASYNC16(sbm + soff, B3 + (size_t)(n0 + row) * K3 + k0 + c8 * 8);
        }
    };

    const int NIT = K3 / 64;                         // 48
    load_stage(0, 0); CP_COMMIT();
    load_stage(1, 1); CP_COMMIT();

    for (int kt = 0; kt < NIT; kt++) {
        CP_WAIT1();
        __syncthreads();
        const int slot = kt % GEMM_STAGES;
        if (kt + 2 < NIT) load_stage((kt + 2) % GEMM_STAGES, kt + 2);
        CP_COMMIT();

        const uint32_t sa  = sb + (uint32_t)slot * 32768u;
        const uint32_t sbm = sa + 16384u;
        const int matA = lane >> 3, lr = lane & 7;

        #pragma unroll
        for (int ks = 0; ks < 4; ks++) {
            uint32_t a[2][4];
            #pragma unroll
            for (int mi = 0; mi < 2; mi++) {
                const int r = wm * 32 + mi * 16 + ((matA & 1) << 3) + lr;
                const int ch = ks * 2 + (matA >> 1);
                ldmx4(a[mi], sa + (uint32_t)(r * 128 + ((ch ^ (r & 7)) << 4)));
            }
            uint32_t bf[8][2];
            #pragma unroll
            for (int np = 0; np < 4; np++) {
                const int r = wn * 64 + np * 16 + ((matA >> 1) << 3) + lr;
                const int ch = ks * 2 + (matA & 1);
                uint32_t q[4];
                ldmx4(q, sbm + (uint32_t)(r * 128 + ((ch ^ (r & 7)) << 4)));
                bf[np*2+0][0] = q[0]; bf[np*2+0][1] = q[1];
                bf[np*2+1][0] = q[2]; bf[np*2+1][1] = q[3];
            }
            #pragma unroll
            for (int mi = 0; mi < 2; mi++)
                #pragma unroll
                for (int ni = 0; ni < 8; ni++)
                    mma_bf16(acc[mi][ni], a[mi], bf[ni]);
        }
        __syncthreads();
    }

    // epilogue
    const int tr = lane >> 2, tc = (lane & 3) << 1;
    #pragma unroll
    for (int mi = 0; mi < 2; mi++) {
        #pragma unroll
        for (int ni = 0; ni < 8; ni++) {
            const int row = m0 + wm * 32 + mi * 16 + tr;
            const int col = n0 + wn * 64 + ni * 8 + tc;
            #pragma unroll
            for (int half = 0; half < 2; half++) {
                const int rr = row + half * 8;
                size_t idx;
                if (HEAD_LAYOUT) {
                    int b = rr >> 11, s2 = rr & (SEQ - 1);
                    int h = col >> 6,  d = col & (HD - 1);
                    idx = ((size_t)((b * NH + h) * SEQ + s2)) * HD + d;
                } else {
                    idx = (size_t)rr * DM + col;
                }
                *(float2*)(C + idx) =
                    make_float2(acc[mi][ni][half*2+0], acc[mi][ni][half*2+1]);
            }
        }
    }
}

// ---------------------------------------------------------------------------
// Causal flash attention, fp32 (unchanged from passing R1 kernel).
// ---------------------------------------------------------------------------
__global__ void __launch_bounds__(256) flash_attn(
    const float* __restrict__ Q, const float* __restrict__ K,
    const float* __restrict__ V, float* __restrict__ A)
{
    __shared__ float QsT[64][64];
    __shared__ float KsT[64][64];
    __shared__ float Vs[64][64];

    const int qt = blockIdx.x;
    const int bh = blockIdx.y;
    const int b  = bh >> 4, h = bh & 15;
    const float* Qb = Q + (size_t)bh * SEQ * HD;
    const float* Kb = K + (size_t)bh * SEQ * HD;
    const float* Vb = V + (size_t)bh * SEQ * HD;

    const int tid = threadIdx.x;
    const int tx = tid & 15, ty = tid >> 4;
    const int lr = tid >> 2;
    const int lc = (tid & 3) << 4;

    {
        const float* qp = Qb + (size_t)(qt * 64 + lr) * HD + lc;
        #pragma unroll
        for (int u = 0; u < 4; u++) {
            float4 v = *(const float4*)(qp + u * 4);
            QsT[lc + u*4 + 0][lr] = v.x;
            QsT[lc + u*4 + 1][lr] = v.y;
            QsT[lc + u*4 + 2][lr] = v.z;
            QsT[lc + u*4 + 3][lr] = v.w;
        }
    }

    float m_[4], l_[4], o[4][4];
    #pragma unroll
    for (int i = 0; i < 4; i++) {
        m_[i] = -1e30f; l_[i] = 0.f;
        #pragma unroll
        for (int j = 0; j < 4; j++) o[i][j] = 0.f;
    }

    for (int kt = 0; kt <= qt; kt++) {
        __syncthreads();
        {
            const float* kp = Kb + (size_t)(kt * 64 + lr) * HD + lc;
            const float* vp = Vb + (size_t)(kt * 64 + lr) * HD + lc;
            #pragma unroll
            for (int u = 0; u < 4; u++) {
                float4 kv = *(const float4*)(kp + u * 4);
                KsT[lc + u*4 + 0][lr] = kv.x;
                KsT[lc + u*4 + 1][lr] = kv.y;
                KsT[lc + u*4 + 2][lr] = kv.z;
                KsT[lc + u*4 + 3][lr] = kv.w;
                float4 vv = *(const float4*)(vp + u * 4);
                *(float4*)&Vs[lr][lc + u * 4] = vv;
            }
        }
        __syncthreads();

        float s[4][4];
        #pragma unroll
        for (int i = 0; i < 4; i++)
            #pragma unroll
            for (int j = 0; j < 4; j++) s[i][j] = 0.f;

        #pragma unroll 8
        for (int k = 0; k < 64; k++) {
            float4 a  = *(const float4*)&QsT[k][ty << 2];
            float4 bk = *(const float4*)&KsT[k][tx << 2];
            s[0][0] += a.x*bk.x; s[0][1] += a.x*bk.y; s[0][2] += a.x*bk.z; s[0][3] += a.x*bk.w;
            s[1][0] += a.y*bk.x; s[1][1] += a.y*bk.y; s[1][2] += a.y*bk.z; s[1][3] += a.y*bk.w;
            s[2][0] += a.z*bk.x; s[2][1] += a.z*bk.y; s[2][2] += a.z*bk.z; s[2][3] += a.z*bk.w;
            s[3][0] += a.w*bk.x; s[3][1] += a.w*bk.y; s[3][2] += a.w*bk.z; s[3][3] += a.w*bk.w;
        }

        float p[4][4];
        const bool diag = (kt == qt);
        #pragma unroll
        for (int i = 0; i < 4; i++) {
            float rmax = -1e30f;
            #pragma unroll
            for (int j = 0; j < 4; j++) {
                float sc = s[i][j] * 0.125f;
                if (diag && ((tx << 2) + j) > ((ty << 2) + i)) sc = -1e8f;
                s[i][j] = sc;
                rmax = fmaxf(rmax, sc);
            }
            #pragma unroll
            for (int off = 8; off > 0; off >>= 1)
                rmax = fmaxf(rmax, __shfl_xor_sync(0xffffffffu, rmax, off));
            float nm = fmaxf(m_[i], rmax);
            float alpha = __expf(m_[i] - nm);
            float rsum = 0.f;
            #pragma unroll
            for (int j = 0; j < 4; j++) {
                float pv = __expf(s[i][j] - nm);
                p[i][j] = pv;
                rsum += pv;
            }
            #pragma unroll
            for (int off = 8; off > 0; off >>= 1)
                rsum += __shfl_xor_sync(0xffffffffu, rsum, off);
            l_[i] = l_[i] * alpha + rsum;
            m_[i] = nm;
            #pragma unroll
            for (int j = 0; j < 4; j++) o[i][j] *= alpha;
        }

        __syncthreads();
        float* Ps = &KsT[0][0];
        #pragma unroll
        for (int i = 0; i < 4; i++)
            *(float4*)&Ps[(((ty << 2) + i) << 6) + (tx << 2)] =
                make_float4(p[i][0], p[i][1], p[i][2], p[i][3]);
        __syncthreads();

        #pragma unroll 8
        for (int kk = 0; kk < 64; kk++) {
            float4 v = *(const float4*)&Vs[kk][tx << 2];
            #pragma unroll
            for (int i = 0; i < 4; i++) {
                float pv = Ps[(((ty << 2) + i) << 6) + kk];
                o[i][0] += pv * v.x;
                o[i][1] += pv * v.y;
                o[i][2] += pv * v.z;
                o[i][3] += pv * v.w;
            }
        }
    }

    #pragma unroll
    for (int i = 0; i < 4; i++) {
        float inv = 1.0f / l_[i];
        int qrow = qt * 64 + (ty << 2) + i;
        float* op = A + ((size_t)(b * SEQ + qrow)) * DM + h * HD + (tx << 2);
        *(float4*)op = make_float4(o[i][0]*inv, o[i][1]*inv, o[i][2]*inv, o[i][3]*inv);
    }
}

// ---------------------------------------------------------------------------

extern "C" void kernel_launch(void* const* d_in, const int* in_sizes, int n_in,
                              void* d_out, int out_size)
{
    (void)in_sizes; (void)n_in; (void)out_size;
    const float* x  = (const float*)d_in[0];
    const float* wq = (const float*)d_in[1];
    const float* wk = (const float*)d_in[2];
    const float* wv = (const float*)d_in[3];
    const float* wo = (const float*)d_in[4];

    float *q, *k, *v, *a;
    __nv_bfloat16 *x3, *w3, *a3;
    cudaGetSymbolAddress((void**)&q,  g_Q);
    cudaGetSymbolAddress((void**)&k,  g_K);
    cudaGetSymbolAddress((void**)&v,  g_V);
    cudaGetSymbolAddress((void**)&a,  g_A);
    cudaGetSymbolAddress((void**)&x3, g_X3);
    cudaGetSymbolAddress((void**)&w3, g_W3);
    cudaGetSymbolAddress((void**)&a3, g_A3);

    static bool attr_set = false;
    if (!attr_set) {
        cudaFuncSetAttribute(gemm_hmma<true>,
                             cudaFuncAttributeMaxDynamicSharedMemorySize, GEMM_SMEM);
        cudaFuncSetAttribute(gemm_hmma<false>,
                             cudaFuncAttributeMaxDynamicSharedMemorySize, GEMM_SMEM);
        attr_set = true;
    }

    // Split fp32 -> triple-interleaved bf16
    const float* ws[4] = { wq, wk, wv, wo };
    split3<true ><<<1024, 256>>>(x, x3, MROWS * DM / 2);
    for (int i = 0; i < 4; i++)
        split3<false><<<512, 256>>>(ws[i], w3 + (size_t)i * DM * K3, DM * DM / 2);

    // QKV projections (HMMA bf16, triple-split), out in [b,h,s,d]
    dim3 blk(256);
    dim3 grid_g(DM / 128, MROWS / 128);    // (8, 32)
    gemm_hmma<true><<<grid_g, blk, GEMM_SMEM>>>(x3, w3 + 0 * (size_t)DM * K3, q);
    gemm_hmma<true><<<grid_g, blk, GEMM_SMEM>>>(x3, w3 + 1 * (size_t)DM * K3, k);
    gemm_hmma<true><<<grid_g, blk, GEMM_SMEM>>>(x3, w3 + 2 * (size_t)DM * K3, v);

    // Attention (fp32 flash)
    dim3 grid_a(SEQ / 64, BATCH * NH);     // (32, 32)
    flash_attn<<<grid_a, blk>>>(q, k, v, a);

    // Split attention output, then O-projection
    split3<true ><<<1024, 256>>>(a, a3, MROWS * DM / 2);
    gemm_hmma<false><<<grid_g, blk, GEMM_SMEM>>>(
        a3, w3 + 3 * (size_t)DM * K3, (float*)d_out);
}

// round 12
// speedup vs baseline: 3.2101x; 1.8884x over previous
#include <cuda_runtime.h>
#include <cuda_bf16.h>
#include <cstdint>

#define BATCH 2
#define SEQ   2048
#define DM    1024
#define NH    16
#define HD    64
#define MROWS (BATCH*SEQ)
#define K3    (3*DM)

typedef __nv_bfloat16 bf16;

// ---------------------------------------------------------------------------
// Scratch (allocation-free rule: __device__ globals)
// ---------------------------------------------------------------------------
__device__ float g_Q[BATCH*NH*SEQ*HD];
__device__ float g_K[BATCH*NH*SEQ*HD];
__device__ float g_V[BATCH*NH*SEQ*HD];
__device__ float g_A[MROWS*DM];
__device__ bf16 g_X3[(size_t)MROWS*K3];
__device__ bf16 g_W3[(size_t)4*DM*K3];
__device__ bf16 g_A3[(size_t)MROWS*K3];
__device__ bf16 g_Qh[BATCH*NH*SEQ*HD];
__device__ bf16 g_Ql[BATCH*NH*SEQ*HD];
__device__ bf16 g_Kh[BATCH*NH*SEQ*HD];
__device__ bf16 g_Kl[BATCH*NH*SEQ*HD];
__device__ bf16 g_Vth[BATCH*NH*HD*SEQ];   // transposed [bh, d, s]
__device__ bf16 g_Vtl[BATCH*NH*HD*SEQ];

// ---------------------------------------------------------------------------
// helpers
// ---------------------------------------------------------------------------
#define CP_ASYNC16(dst, src) \
    asm volatile("cp.async.cg.shared.global [%0], [%1], 16;" :: "r"(dst), "l"(src))
#define CP_COMMIT() asm volatile("cp.async.commit_group;" ::: "memory")
#define CP_WAIT1()  asm volatile("cp.async.wait_group 1;" ::: "memory")

__device__ __forceinline__ uint32_t smem_u32(const void* p) {
    uint32_t a;
    asm("{ .reg .u64 t; cvta.to.shared.u64 t, %1; cvt.u32.u64 %0, t; }" : "=r"(a) : "l"(p));
    return a;
}
__device__ __forceinline__ void ldmx4(uint32_t* r, uint32_t addr) {
    asm volatile("ldmatrix.sync.aligned.m8n8.x4.shared.b16 {%0,%1,%2,%3}, [%4];"
                 : "=r"(r[0]), "=r"(r[1]), "=r"(r[2]), "=r"(r[3]) : "r"(addr));
}
__device__ __forceinline__ void mma_bf16(float* c, const uint32_t* a, const uint32_t* b) {
    asm volatile(
        "mma.sync.aligned.m16n8k16.row.col.f32.bf16.bf16.f32 "
        "{%0,%1,%2,%3}, {%4,%5,%6,%7}, {%8,%9}, {%0,%1,%2,%3};"
        : "+f"(c[0]), "+f"(c[1]), "+f"(c[2]), "+f"(c[3])
        : "r"(a[0]), "r"(a[1]), "r"(a[2]), "r"(a[3]), "r"(b[0]), "r"(b[1]));
}
// pack two fp32 -> bf16x2 (lo = first arg in low 16 bits)
__device__ __forceinline__ uint32_t pack2bf(float lo, float hi) {
    uint32_t r;
    asm("cvt.rn.bf16x2.f32 %0, %1, %2;" : "=r"(r) : "f"(hi), "f"(lo));
    return r;
}

// ---------------------------------------------------------------------------
// fp32 -> triple-interleaved bf16 (for projection GEMMs)
// ---------------------------------------------------------------------------
template<bool A_TYPE>
__global__ void split3(const float* __restrict__ src,
                       bf16* __restrict__ dst, int n2)
{
    int i = blockIdx.x * blockDim.x + threadIdx.x;
    int stride = gridDim.x * blockDim.x;
    __nv_bfloat162* d2 = (__nv_bfloat162*)dst;
    for (; i < n2; i += stride) {
        float2 x = ((const float2*)src)[i];
        bf16 hx = __float2bfloat16(x.x);
        bf16 hy = __float2bfloat16(x.y);
        bf16 lx = __float2bfloat16(x.x - __bfloat162float(hx));
        bf16 ly = __float2bfloat16(x.y - __bfloat162float(hy));
        if (A_TYPE) {
            d2[i*3+0] = __halves2bfloat162(hx, lx);
            d2[i*3+1] = __halves2bfloat162(hx, hy);
            d2[i*3+2] = __halves2bfloat162(ly, hy);
        } else {
            d2[i*3+0] = __halves2bfloat162(hx, hx);
            d2[i*3+1] = __halves2bfloat162(lx, hy);
            d2[i*3+2] = __halves2bfloat162(hy, ly);
        }
    }
}

// fp32 -> (hi, lo) bf16, same layout, with scale
__global__ void split_hl(const float* __restrict__ src,
                         bf16* __restrict__ hi, bf16* __restrict__ lo,
                         float scale, int n2)
{
    int i = blockIdx.x * blockDim.x + threadIdx.x;
    int stride = gridDim.x * blockDim.x;
    for (; i < n2; i += stride) {
        float2 x = ((const float2*)src)[i];
        x.x *= scale; x.y *= scale;
        bf16 hx = __float2bfloat16(x.x);
        bf16 hy = __float2bfloat16(x.y);
        ((__nv_bfloat162*)hi)[i] = __halves2bfloat162(hx, hy);
        ((__nv_bfloat162*)lo)[i] = __halves2bfloat162(
            __float2bfloat16(x.x - __bfloat162float(hx)),
            __float2bfloat16(x.y - __bfloat162float(hy)));
    }
}

// V [bh, s, d] fp32 -> Vt hi/lo [bh, d, s] bf16 (64x64 tile transpose)
__global__ void transpose_split_v(const float* __restrict__ V,
                                  bf16* __restrict__ vth, bf16* __restrict__ vtl)
{
    __shared__ float ts[64][65];
    const int bh = blockIdx.y;
    const int s0 = blockIdx.x * 64;
    const int t = threadIdx.x;
    #pragma unroll
    for (int i = 0; i < 4; i++) {
        int lin = t + i * 256;
        int r = lin >> 4, c = (lin & 15) * 4;
        float4 v = *(const float4*)(V + ((size_t)(bh * SEQ + s0 + r)) * HD + c);
        ts[r][c] = v.x; ts[r][c+1] = v.y; ts[r][c+2] = v.z; ts[r][c+3] = v.w;
    }
    __syncthreads();
    const int d = t >> 2, sseg = (t & 3) * 16;
    size_t ob = ((size_t)(bh * HD + d)) * SEQ + s0 + sseg;
    #pragma unroll
    for (int u = 0; u < 16; u += 2) {
        float v0 = ts[sseg + u][d], v1 = ts[sseg + u + 1][d];
        bf16 h0 = __float2bfloat16(v0), h1 = __float2bfloat16(v1);
        *(__nv_bfloat162*)(vth + ob + u) = __halves2bfloat162(h0, h1);
        *(__nv_bfloat162*)(vtl + ob + u) = __halves2bfloat162(
            __float2bfloat16(v0 - __bfloat162float(h0)),
            __float2bfloat16(v1 - __bfloat162float(h1)));
    }
}

// ---------------------------------------------------------------------------
// bf16 HMMA GEMM (verified, unchanged):  C = A3[M,K3] * B3[N,K3]^T
// ---------------------------------------------------------------------------
#define GEMM_STAGES 3
#define GEMM_SMEM   (GEMM_STAGES * 32768)

template<bool HEAD_LAYOUT>
__global__ void __launch_bounds__(256)
gemm_hmma(const bf16* __restrict__ A3,
          const bf16* __restrict__ B3,
          float* __restrict__ C)
{
    extern __shared__ char dsm[];
    const uint32_t sb = smem_u32(dsm);
    const int t = threadIdx.x;
    const int lane = t & 31, wid = t >> 5;
    const int wm = wid & 3, wn = wid >> 2;
    const int m0 = blockIdx.y << 7, n0 = blockIdx.x << 7;

    float acc[2][8][4];
    #pragma unroll
    for (int mi = 0; mi < 2; mi++)
        #pragma unroll
        for (int ni = 0; ni < 8; ni++)
            #pragma unroll
            for (int j = 0; j < 4; j++) acc[mi][ni][j] = 0.f;

    auto load_stage = [&](int slot, int kt) {
        const uint32_t sa  = sb + (uint32_t)slot * 32768u;
        const uint32_t sbm = sa + 16384u;
        const int k0 = kt << 6;
        #pragma unroll
        for (int i = 0; i < 4; i++) {
            const int lin = t + (i << 8);
            const int row = lin >> 3, c8 = lin & 7;
            const uint32_t soff = (uint32_t)(row * 128 + ((c8 ^ (row & 7)) << 4));
            CP_ASYNC16(sa  + soff, A3 + (size_t)(m0 + row) * K3 + k0 + c8 * 8);
            CP_ASYNC16(sbm + soff, B3 + (size_t)(n0 + row) * K3 + k0 + c8 * 8);
        }
    };

    const int NIT = K3 / 64;
    load_stage(0, 0); CP_COMMIT();
    load_stage(1, 1); CP_COMMIT();

    for (int kt = 0; kt < NIT; kt++) {
        CP_WAIT1();
        __syncthreads();
        const int slot = kt % GEMM_STAGES;
        if (kt + 2 < NIT) load_stage((kt + 2) % GEMM_STAGES, kt + 2);
        CP_COMMIT();

        const uint32_t sa  = sb + (uint32_t)slot * 32768u;
        const uint32_t sbm = sa + 16384u;
        const int matA = lane >> 3, lr = lane & 7;

        #pragma unroll
        for (int ks = 0; ks < 4; ks++) {
            uint32_t a[2][4];
            #pragma unroll
            for (int mi = 0; mi < 2; mi++) {
                const int r = wm * 32 + mi * 16 + ((matA & 1) << 3) + lr;
                const int ch = ks * 2 + (matA >> 1);
                ldmx4(a[mi], sa + (uint32_t)(r * 128 + ((ch ^ (r & 7)) << 4)));
            }
            uint32_t bf[8][2];
            #pragma unroll
            for (int np = 0; np < 4; np++) {
                const int r = wn * 64 + np * 16 + ((matA >> 1) << 3) + lr;
                const int ch = ks * 2 + (matA & 1);
                uint32_t q[4];
                ldmx4(q, sbm + (uint32_t)(r * 128 + ((ch ^ (r & 7)) << 4)));
                bf[np*2+0][0] = q[0]; bf[np*2+0][1] = q[1];
                bf[np*2+1][0] = q[2]; bf[np*2+1][1] = q[3];
            }
            #pragma unroll
            for (int mi = 0; mi < 2; mi++)
                #pragma unroll
                for (int ni = 0; ni < 8; ni++)
                    mma_bf16(acc[mi][ni], a[mi], bf[ni]);
        }
        __syncthreads();
    }

    const int tr = lane >> 2, tc = (lane & 3) << 1;
    #pragma unroll
    for (int mi = 0; mi < 2; mi++) {
        #pragma unroll
        for (int ni = 0; ni < 8; ni++) {
            const int row = m0 + wm * 32 + mi * 16 + tr;
            const int col = n0 + wn * 64 + ni * 8 + tc;
            #pragma unroll
            for (int half = 0; half < 2; half++) {
                const int rr = row + half * 8;
                size_t idx;
                if (HEAD_LAYOUT) {
                    int b = rr >> 11, s2 = rr & (SEQ - 1);
                    int h = col >> 6,  d = col & (HD - 1);
                    idx = ((size_t)((b * NH + h) * SEQ + s2)) * HD + d;
                } else {
                    idx = (size_t)rr * DM + col;
                }
                *(float2*)(C + idx) =
                    make_float2(acc[mi][ni][half*2+0], acc[mi][ni][half*2+1]);
            }
        }
    }
}

// ---------------------------------------------------------------------------
// Tensor-core causal flash attention.
// CTA: 128 q-rows x 8 warps (warp = m16 x n64), k-tiles of 64.
// S = Qhi*Khi + Qhi*Klo + Qlo*Khi (Q pre-scaled by 1/8).
// P split in registers (acc layout == A-frag layout): O += Phi*Vhi+Phi*Vlo+Plo*Vhi.
// Double-buffered cp.async K/V stages. Output [b, s, h*d].
// ---------------------------------------------------------------------------
#define FA_SMEM (32768 + 2*32768)

__global__ void __launch_bounds__(256, 2)
flash_hmma(const bf16* __restrict__ Qh, const bf16* __restrict__ Ql,
           const bf16* __restrict__ Kh, const bf16* __restrict__ Kl,
           const bf16* __restrict__ Vth, const bf16* __restrict__ Vtl,
           float* __restrict__ A)
{
    extern __shared__ char dsmf[];
    const uint32_t sb = smem_u32(dsmf);
    const uint32_t sQh = sb, sQl = sb + 16384u;

    const int t = threadIdx.x;
    const int lane = t & 31, wid = t >> 5;
    const int matA = lane >> 3, lr = lane & 7;
    const int qt = 15 - blockIdx.x;           // big tiles first
    const int bh = blockIdx.y;
    const int qbase = qt * 128;
    const int wr = qbase + wid * 16;          // warp's first q row
    const int nkt = 2 * qt + 2;

    const size_t qoff = (size_t)(bh * SEQ + qbase) * HD;
    const size_t koff = (size_t)bh * SEQ * HD;
    const size_t voff = (size_t)bh * HD * SEQ;

    auto load_stage = [&](int slot, int kt) {
        const uint32_t st = sb + 32768u + (uint32_t)slot * 32768u;
        const int kb = kt * 64;
        #pragma unroll
        for (int i = 0; i < 2; i++) {
            const int lin = t + (i << 8);
            const int row = lin >> 3, c8 = lin & 7;
            const uint32_t soff = (uint32_t)(row * 128 + ((c8 ^ (row & 7)) << 4));
            CP_ASYNC16(st + soff,           Kh  + koff + (size_t)(kb + row) * HD + c8 * 8);
            CP_ASYNC16(st + 8192u  + soff,  Kl  + koff + (size_t)(kb + row) * HD + c8 * 8);
            CP_ASYNC16(st + 16384u + soff,  Vth + voff + (size_t)row * SEQ + kb + c8 * 8);
            CP_ASYNC16(st + 24576u + soff,  Vtl + voff + (size_t)row * SEQ + kb + c8 * 8);
        }
    };

    // Q tiles (hi+lo), loaded once
    #pragma unroll
    for (int i = 0; i < 4; i++) {
        const int lin = t + (i << 8);
        const int row = lin >> 3, c8 = lin & 7;
        const uint32_t soff = (uint32_t)(row * 128 + ((c8 ^ (row & 7)) << 4));
        CP_ASYNC16(sQh + soff, Qh + qoff + (size_t)row * HD + c8 * 8);
        CP_ASYNC16(sQl + soff, Ql + qoff + (size_t)row * HD + c8 * 8);
    }
    load_stage(0, 0); CP_COMMIT();
    load_stage(1, 1); CP_COMMIT();

    float o[8][4];
    #pragma unroll
    for (int ni = 0; ni < 8; ni++)
        #pragma unroll
        for (int j = 0; j < 4; j++) o[ni][j] = 0.f;
    float m0 = -1e30f, m1 = -1e30f, l0 = 0.f, l1 = 0.f;

    for (int kt = 0; kt < nkt; kt++) {
        CP_WAIT1();
        __syncthreads();
        const int ktb = kt * 64;
        const uint32_t st = sb + 32768u + (uint32_t)(kt & 1) * 32768u;

        if (ktb <= wr + 15) {                 // warp not fully above diagonal
            // ---- S = Q K^T (3 compensated passes) ----
            float s[8][4];
            #pragma unroll
            for (int ni = 0; ni < 8; ni++)
                #pragma unroll
                for (int j = 0; j < 4; j++) s[ni][j] = 0.f;

            #pragma unroll
            for (int ks = 0; ks < 4; ks++) {
                uint32_t ah[4], al[4];
                {
                    const int r = wid * 16 + ((matA & 1) << 3) + lr;
                    const int ch = ks * 2 + (matA >> 1);
                    const uint32_t off = (uint32_t)(r * 128 + ((ch ^ (r & 7)) << 4));
                    ldmx4(ah, sQh + off);
                    ldmx4(al, sQl + off);
                }
                #pragma unroll
                for (int nb = 0; nb < 4; nb++) {
                    const int r2 = nb * 16 + ((matA >> 1) << 3) + lr;
                    const int ch2 = ks * 2 + (matA & 1);
                    const uint32_t off2 = (uint32_t)(r2 * 128 + ((ch2 ^ (r2 & 7)) << 4));
                    uint32_t kh4[4], kl4[4];
                    ldmx4(kh4, st + off2);
                    ldmx4(kl4, st + 8192u + off2);
                    mma_bf16(s[2*nb],   ah, kh4);
                    mma_bf16(s[2*nb+1], ah, kh4 + 2);
                    mma_bf16(s[2*nb],   ah, kl4);
                    mma_bf16(s[2*nb+1], ah, kl4 + 2);
                    mma_bf16(s[2*nb],   al, kh4);
                    mma_bf16(s[2*nb+1], al, kh4 + 2);
                }
            }

            // ---- causal mask (diagonal-overlap tiles only) ----
            const int row0 = wr + (lane >> 2), row1 = row0 + 8;
            if (ktb + 63 > wr) {
                #pragma unroll
                for (int ni = 0; ni < 8; ni++) {
                    const int c0 = ktb + ni * 8 + ((lane & 3) << 1);
                    if (c0     > row0) s[ni][0] = -1e9f;
                    if (c0 + 1 > row0) s[ni][1] = -1e9f;
                    if (c0     > row1) s[ni][2] = -1e9f;
                    if (c0 + 1 > row1) s[ni][3] = -1e9f;
                }
            }

            // ---- online softmax (row stats in regs, 4-lane shfl reduce) ----
            float rx0 = -1e30f, rx1 = -1e30f;
            #pragma unroll
            for (int ni = 0; ni < 8; ni++) {
                rx0 = fmaxf(rx0, fmaxf(s[ni][0], s[ni][1]));
                rx1 = fmaxf(rx1, fmaxf(s[ni][2], s[ni][3]));
            }
            rx0 = fmaxf(rx0, __shfl_xor_sync(0xffffffffu, rx0, 1));
            rx0 = fmaxf(rx0, __shfl_xor_sync(0xffffffffu, rx0, 2));
            rx1 = fmaxf(rx1, __shfl_xor_sync(0xffffffffu, rx1, 1));
            rx1 = fmaxf(rx1, __shfl_xor_sync(0xffffffffu, rx1, 2));
            const float nm0 = fmaxf(m0, rx0), nm1 = fmaxf(m1, rx1);
            const float a0 = __expf(m0 - nm0), a1 = __expf(m1 - nm1);
            float sum0 = 0.f, sum1 = 0.f;
            #pragma unroll
            for (int ni = 0; ni < 8; ni++) {
                s[ni][0] = __expf(s[ni][0] - nm0);
                s[ni][1] = __expf(s[ni][1] - nm0);
                s[ni][2] = __expf(s[ni][2] - nm1);
                s[ni][3] = __expf(s[ni][3] - nm1);
                sum0 += s[ni][0] + s[ni][1];
                sum1 += s[ni][2] + s[ni][3];
            }
            sum0 += __shfl_xor_sync(0xffffffffu, sum0, 1);
            sum0 += __shfl_xor_sync(0xffffffffu, sum0, 2);
            sum1 += __shfl_xor_sync(0xffffffffu, sum1, 1);
            sum1 += __shfl_xor_sync(0xffffffffu, sum1, 2);
            l0 = l0 * a0 + sum0;  m0 = nm0;
            l1 = l1 * a1 + sum1;  m1 = nm1;
            #pragma unroll
            for (int ni = 0; ni < 8; ni++) {
                o[ni][0] *= a0; o[ni][1] *= a0;
                o[ni][2] *= a1; o[ni][3] *= a1;
            }

            // ---- O += P V (P in registers, hi/lo compensated) ----
            #pragma unroll
            for (int j = 0; j < 4; j++) {
                uint32_t ph[4], pl[4];
                #pragma unroll
                for (int q2 = 0; q2 < 2; q2++) {          // k-lo (tile 2j) / k-hi (2j+1)
                    const float c0 = s[2*j + q2][0], c1 = s[2*j + q2][1];
                    const float c2 = s[2*j + q2][2], c3 = s[2*j + q2][3];
                    const uint32_t h01 = pack2bf(c0, c1);
                    const uint32_t h23 = pack2bf(c2, c3);
                    ph[q2*2 + 0] = h01 << 16 >> 16 | (h01 & 0xffff0000u);  // identity (keep)
                    ph[q2*2 + 0] = h01;
                    ph[q2*2 + 1] = h23;
                    __nv_bfloat162 hb01 = *(__nv_bfloat162*)&h01;
                    __nv_bfloat162 hb23 = *(__nv_bfloat162*)&h23;
                    float2 f01 = __bfloat1622float2(hb01);
                    float2 f23 = __bfloat1622float2(hb23);
                    pl[q2*2 + 0] = pack2bf(c0 - f01.x, c1 - f01.y);
                    pl[q2*2 + 1] = pack2bf(c2 - f23.x, c3 - f23.y);
                }
                // reorder to A-frag: a0 = rowg k-lo, a1 = rowg+8 k-lo, a2 = rowg k-hi, a3 = rowg+8 k-hi
                uint32_t pa_h[4] = { ph[0], ph[1], ph[2], ph[3] };
                uint32_t pa_l[4] = { pl[0], pl[1], pl[2], pl[3] };
                #pragma unroll
                for (int db = 0; db < 4; db++) {
                    const int r2 = db * 16 + ((matA >> 1) << 3) + lr;
                    const int ch2 = j * 2 + (matA & 1);
                    const uint32_t off2 = (uint32_t)(r2 * 128 + ((ch2 ^ (r2 & 7)) << 4));
                    uint32_t vh4[4], vl4[4];
                    ldmx4(vh4, st + 16384u + off2);
                    ldmx4(vl4, st + 24576u + off2);
                    mma_bf16(o[2*db],   pa_h, vh4);
                    mma_bf16(o[2*db+1], pa_h, vh4 + 2);
                    mma_bf16(o[2*db],   pa_h, vl4);
                    mma_bf16(o[2*db+1], pa_h, vl4 + 2);
                    mma_bf16(o[2*db],   pa_l, vh4);
                    mma_bf16(o[2*db+1], pa_l, vh4 + 2);
                }
            }
        }

        __syncthreads();
        if (kt + 2 < nkt) load_stage(kt & 1, kt + 2);
        CP_COMMIT();
    }

    // ---- epilogue: normalize, write [b, s, h*d] ----
    const float inv0 = 1.0f / l0, inv1 = 1.0f / l1;
    const int b = bh >> 4, h = bh & 15;
    const int srow0 = qbase + wid * 16 + (lane >> 2);
    const size_t base0 = ((size_t)(b * SEQ + srow0)) * DM + h * HD;
    const size_t base1 = base0 + (size_t)8 * DM;
    #pragma unroll
    for (int ni = 0; ni < 8; ni++) {
        const int col = ni * 8 + ((lane & 3) << 1);
        *(float2*)(A + base0 + col) = make_float2(o[ni][0] * inv0, o[ni][1] * inv0);
        *(float2*)(A + base1 + col) = make_float2(o[ni][2] * inv1, o[ni][3] * inv1);
    }
}

// ---------------------------------------------------------------------------

extern "C" void kernel_launch(void* const* d_in, const int* in_sizes, int n_in,
                              void* d_out, int out_size)
{
    (void)in_sizes; (void)n_in; (void)out_size;
    const float* x  = (const float*)d_in[0];
    const float* wq = (const float*)d_in[1];
    const float* wk = (const float*)d_in[2];
    const float* wv = (const float*)d_in[3];
    const float* wo = (const float*)d_in[4];

    float *q, *k, *v, *a;
    bf16 *x3, *w3, *a3, *qh, *ql, *kh, *kl, *vth, *vtl;
    cudaGetSymbolAddress((void**)&q,  g_Q);
    cudaGetSymbolAddress((void**)&k,  g_K);
    cudaGetSymbolAddress((void**)&v,  g_V);
    cudaGetSymbolAddress((void**)&a,  g_A);
    cudaGetSymbolAddress((void**)&x3, g_X3);
    cudaGetSymbolAddress((void**)&w3, g_W3);
    cudaGetSymbolAddress((void**)&a3, g_A3);
    cudaGetSymbolAddress((void**)&qh, g_Qh);
    cudaGetSymbolAddress((void**)&ql, g_Ql);
    cudaGetSymbolAddress((void**)&kh, g_Kh);
    cudaGetSymbolAddress((void**)&kl, g_Kl);
    cudaGetSymbolAddress((void**)&vth, g_Vth);
    cudaGetSymbolAddress((void**)&vtl, g_Vtl);

    static bool attr_set = false;
    if (!attr_set) {
        cudaFuncSetAttribute(gemm_hmma<true>,
                             cudaFuncAttributeMaxDynamicSharedMemorySize, GEMM_SMEM);
        cudaFuncSetAttribute(gemm_hmma<false>,
                             cudaFuncAttributeMaxDynamicSharedMemorySize, GEMM_SMEM);
        cudaFuncSetAttribute(flash_hmma,
                             cudaFuncAttributeMaxDynamicSharedMemorySize, FA_SMEM);
        attr_set = true;
    }

    // Split fp32 -> triple-interleaved bf16 for projections
    const float* ws[4] = { wq, wk, wv, wo };
    split3<true ><<<1024, 256>>>(x, x3, MROWS * DM / 2);
    for (int i = 0; i < 4; i++)
        split3<false><<<512, 256>>>(ws[i], w3 + (size_t)i * DM * K3, DM * DM / 2);

    // QKV projections, out fp32 in [b,h,s,d]
    dim3 blk(256);
    dim3 grid_g(DM / 128, MROWS / 128);
    gemm_hmma<true><<<grid_g, blk, GEMM_SMEM>>>(x3, w3 + 0 * (size_t)DM * K3, q);
    gemm_hmma<true><<<grid_g, blk, GEMM_SMEM>>>(x3, w3 + 1 * (size_t)DM * K3, k);
    gemm_hmma<true><<<grid_g, blk, GEMM_SMEM>>>(x3, w3 + 2 * (size_t)DM * K3, v);

    // Prep for tensor-core flash: Q scaled+split, K split, V transposed+split
    const int nqk2 = BATCH * NH * SEQ * HD / 2;
    split_hl<<<1024, 256>>>(q, qh, ql, 0.125f, nqk2);
    split_hl<<<1024, 256>>>(k, kh, kl, 1.0f,  nqk2);
    transpose_split_v<<<dim3(SEQ / 64, BATCH * NH), 256>>>(v, vth, vtl);

    // Tensor-core flash attention
    flash_hmma<<<dim3(SEQ / 128, BATCH * NH), blk, FA_SMEM>>>(
        qh, ql, kh, kl, vth, vtl, a);

    // O-projection
    split3<true ><<<1024, 256>>>(a, a3, MROWS * DM / 2);
    gemm_hmma<false><<<grid_g, blk, GEMM_SMEM>>>(
        a3, w3 + 3 * (size_t)DM * K3, (float*)d_out);
}